// round 10
// baseline (speedup 1.0000x reference)
#include <cuda_runtime.h>
#include <math.h>
#include <stdint.h>

#define B_    4
#define T_    2048
#define C_    1024
#define H_    16
#define D_    64
#define WIN_  256

// Scratch (device globals; no runtime allocation allowed)
__device__ float g_q[B_*H_*T_*D_];
__device__ float g_k[B_*H_*T_*D_];
__device__ float g_v[B_*H_*T_*D_];
__device__ float g_att[B_*T_*C_];

__device__ __forceinline__ uint32_t f2tf32(float x) {
    uint32_t r;
    asm("cvt.rna.tf32.f32 %0, %1;" : "=r"(r) : "f"(x));
    return r;
}

__device__ __forceinline__ void mma_tf32_16x8x8(
    float* d, const uint32_t* a, const uint32_t* b)
{
    asm volatile(
        "mma.sync.aligned.m16n8k8.row.col.f32.tf32.tf32.f32 "
        "{%0,%1,%2,%3}, {%4,%5,%6,%7}, {%8,%9}, {%0,%1,%2,%3};"
        : "+f"(d[0]), "+f"(d[1]), "+f"(d[2]), "+f"(d[3])
        : "r"(a[0]), "r"(a[1]), "r"(a[2]), "r"(a[3]),
          "r"(b[0]), "r"(b[1]));
}

// ---------------------------------------------------------------------------
// tf32 tensor-core GEMM, NT: C[m,n] = sum_k A[m,k]*Bw[n,k] + bias[n]
// Block tile 128x128x32, 256 threads, warp tile 64x32.
// DOUBLE-BUFFERED smem (dynamic, 2 x 36.9KB): one __syncthreads per chunk.
//   iter c: mma reads buf c&1; LDG of chunk c+1 in flight; STS writes buf
//   (c+1)&1; sync. (Safe: mma.sync is register-synchronous, so all reads of
//   a buffer complete before the warp reaches the barrier.)
// Layout [m][k] stride 36: coalesced LDG, STS.128 conflict-free, fragment
// LDS banks 4g+q all distinct.
// MODE 0: plain write. MODE 1: qkv scatter. MODE 2: A = g_att (device-bound;
// host-passed __device__ symbols silently read the host shadow via ATS).
// ---------------------------------------------------------------------------
#define KPAD 36
#define BUFW (2 * 128 * KPAD)                 // words per buffer (A+B)
#define GSMEM_BYTES (2 * BUFW * 4)            // 73728 B

template<int MODE>
__global__ __launch_bounds__(256, 2) void gemm_tf32(
    const float* __restrict__ Aarg,
    const float* __restrict__ Bw,
    const float* __restrict__ bias,
    float* __restrict__ Cout,
    int M, int N, int K)
{
    extern __shared__ uint32_t sm[];

    const float* __restrict__ A = (MODE == 2) ? (const float*)g_att : Aarg;

    const int tid  = threadIdx.x;
    const int w    = tid >> 5;
    const int lane = tid & 31;
    const int gid  = lane >> 2;
    const int qid  = lane & 3;
    const int wm   = w & 1;
    const int wn   = w >> 1;
    const int m0   = blockIdx.y * 128;
    const int n0   = blockIdx.x * 128;

    // Staging map (coalesced LDG): f = tid + it*256
    int srow[4], sk4[4];
    #pragma unroll
    for (int it = 0; it < 4; it++) {
        int f = tid + it * 256;
        srow[it] = f >> 3;
        sk4[it]  = (f & 7) << 2;
    }

    float acc[4][4][4];
    #pragma unroll
    for (int i = 0; i < 4; i++)
        #pragma unroll
        for (int j = 0; j < 4; j++)
            #pragma unroll
            for (int r = 0; r < 4; r++) acc[i][j][r] = 0.f;

    float4 ra[4], rb[4];
    #pragma unroll
    for (int it = 0; it < 4; it++) {
        ra[it] = *(const float4*)&A [(long)(m0 + srow[it]) * K + sk4[it]];
        rb[it] = *(const float4*)&Bw[(long)(n0 + srow[it]) * K + sk4[it]];
    }

    // Stage chunk 0 into buffer 0
    {
        uint32_t* As = sm;
        uint32_t* Bs = sm + 128 * KPAD;
        #pragma unroll
        for (int it = 0; it < 4; it++) {
            const int r = srow[it], k4 = sk4[it];
            uint4 ua, ub;
            ua.x = f2tf32(ra[it].x); ua.y = f2tf32(ra[it].y);
            ua.z = f2tf32(ra[it].z); ua.w = f2tf32(ra[it].w);
            ub.x = f2tf32(rb[it].x); ub.y = f2tf32(rb[it].y);
            ub.z = f2tf32(rb[it].z); ub.w = f2tf32(rb[it].w);
            *(uint4*)&As[r * KPAD + k4] = ua;
            *(uint4*)&Bs[r * KPAD + k4] = ub;
        }
    }
    __syncthreads();

    const int nch = K / 32;
    for (int c = 0; c < nch; c++) {
        uint32_t* As = sm + (c & 1) * BUFW;
        uint32_t* Bs = As + 128 * KPAD;

        // LDG chunk c+1 (in flight during mma)
        const bool more = (c + 1 < nch);
        if (more) {
            const int k0 = (c + 1) * 32;
            #pragma unroll
            for (int it = 0; it < 4; it++) {
                ra[it] = *(const float4*)&A [(long)(m0 + srow[it]) * K + k0 + sk4[it]];
                rb[it] = *(const float4*)&Bw[(long)(n0 + srow[it]) * K + k0 + sk4[it]];
            }
        }

        #pragma unroll
        for (int kk = 0; kk < 4; kk++) {
            const int kb = kk * 8;
            uint32_t af[4][4], bf[4][2];
            #pragma unroll
            for (int im = 0; im < 4; im++) {
                const int mr = wm * 64 + im * 16 + gid;
                af[im][0] = As[ mr      * KPAD + kb + qid];
                af[im][1] = As[(mr + 8) * KPAD + kb + qid];
                af[im][2] = As[ mr      * KPAD + kb + qid + 4];
                af[im][3] = As[(mr + 8) * KPAD + kb + qid + 4];
            }
            #pragma unroll
            for (int in = 0; in < 4; in++) {
                const int nc = wn * 32 + in * 8 + gid;
                bf[in][0] = Bs[nc * KPAD + kb + qid];
                bf[in][1] = Bs[nc * KPAD + kb + qid + 4];
            }
            #pragma unroll
            for (int im = 0; im < 4; im++)
                #pragma unroll
                for (int in = 0; in < 4; in++)
                    mma_tf32_16x8x8(acc[im][in], af[im], bf[in]);
        }

        // STS chunk c+1 into the OTHER buffer (no barrier needed before)
        if (more) {
            uint32_t* An = sm + ((c + 1) & 1) * BUFW;
            uint32_t* Bn = An + 128 * KPAD;
            #pragma unroll
            for (int it = 0; it < 4; it++) {
                const int r = srow[it], k4 = sk4[it];
                uint4 ua, ub;
                ua.x = f2tf32(ra[it].x); ua.y = f2tf32(ra[it].y);
                ua.z = f2tf32(ra[it].z); ua.w = f2tf32(ra[it].w);
                ub.x = f2tf32(rb[it].x); ub.y = f2tf32(rb[it].y);
                ub.z = f2tf32(rb[it].z); ub.w = f2tf32(rb[it].w);
                *(uint4*)&An[r * KPAD + k4] = ua;
                *(uint4*)&Bn[r * KPAD + k4] = ub;
            }
            __syncthreads();
        }
    }

    // Epilogue: c0:(gid,2q) c1:(gid,2q+1) c2:(gid+8,2q) c3:(gid+8,2q+1)
    #pragma unroll
    for (int im = 0; im < 4; im++) {
        #pragma unroll
        for (int in = 0; in < 4; in++) {
            const int mbase = m0 + wm * 64 + im * 16 + gid;
            const int nbase = n0 + wn * 32 + in * 8 + qid * 2;
            #pragma unroll
            for (int r = 0; r < 4; r++) {
                const int m = mbase + (r >> 1) * 8;
                const int n = nbase + (r & 1);
                float v = acc[im][in][r] + bias[n];
                if (MODE == 1) {
                    int s = n >> 10;
                    int h = (n >> 6) & 15;
                    int d = n & 63;
                    int b = m >> 11;
                    int t = m & 2047;
                    float* dst = (s == 0) ? g_q : (s == 1 ? g_k : g_v);
                    dst[(((long)(b * H_ + h)) * T_ + t) * D_ + d] = v;
                } else {
                    Cout[(long)m * N + n] = v;
                }
            }
        }
    }
}

// ---------------------------------------------------------------------------
// Tensor-core windowed attention (unchanged from R8; ~150us).
// ---------------------------------------------------------------------------
#define QT  128
#define CK2 32

__global__ __launch_bounds__(256, 2) void attn_mma_kernel()
{
    __shared__ uint32_t k_s[CK2][68];
    __shared__ uint32_t v_s[64][40];
    __shared__ uint32_t p_s[8][16][40];

    const int tid  = threadIdx.x;
    const int w    = tid >> 5;
    const int lane = tid & 31;
    const int g    = lane >> 2;
    const int q    = lane & 3;
    const int q0   = blockIdx.x * QT;
    const int h    = blockIdx.y;
    const int b    = blockIdx.z;

    const long bh   = (long)(b * H_ + h);
    const float* Qp = g_q + bh * T_ * D_;
    const float* Kp = g_k + bh * T_ * D_;
    const float* Vp = g_v + bh * T_ * D_;

    const int qw  = q0 + w * 16;
    const int qg0 = qw + g;
    const int qg1 = qw + g + 8;

    uint32_t aq[8][4];
    #pragma unroll
    for (int kk = 0; kk < 8; kk++) {
        aq[kk][0] = f2tf32(Qp[(long)qg0 * D_ + kk * 8 + q    ] * 0.125f);
        aq[kk][1] = f2tf32(Qp[(long)qg1 * D_ + kk * 8 + q    ] * 0.125f);
        aq[kk][2] = f2tf32(Qp[(long)qg0 * D_ + kk * 8 + q + 4] * 0.125f);
        aq[kk][3] = f2tf32(Qp[(long)qg1 * D_ + kk * 8 + q + 4] * 0.125f);
    }

    int lo_blk = q0 - (WIN_ - 1);
    if (lo_blk < 0) lo_blk = 0;
    lo_blk &= ~(CK2 - 1);
    const int nchunks = ((q0 + QT - 1) - lo_blk) / CK2 + 1;

    float o[8][4];
    #pragma unroll
    for (int dt = 0; dt < 8; dt++)
        #pragma unroll
        for (int r = 0; r < 4; r++) o[dt][r] = 0.f;
    float m0r = -1e30f, m1r = -1e30f, l0 = 0.f, l1 = 0.f;

    for (int c = 0; c < nchunks; c++) {
        const int ks = lo_blk + c * CK2;
        __syncthreads();
        #pragma unroll
        for (int it = 0; it < 2; it++) {
            int f    = tid + it * 256;
            int j    = f >> 4;
            int qd   = (f & 15) << 2;
            float4 kv = *(const float4*)&Kp[(long)(ks + j) * D_ + qd];
            uint4 uk;
            uk.x = f2tf32(kv.x); uk.y = f2tf32(kv.y);
            uk.z = f2tf32(kv.z); uk.w = f2tf32(kv.w);
            *(uint4*)&k_s[j][qd] = uk;
        }
        #pragma unroll
        for (int it = 0; it < 2; it++) {
            int f   = tid + it * 256;
            int j   = f & 31;
            int dq  = (f >> 5) << 2;
            float4 vv = *(const float4*)&Vp[(long)(ks + j) * D_ + dq];
            v_s[dq + 0][j] = f2tf32(vv.x);
            v_s[dq + 1][j] = f2tf32(vv.y);
            v_s[dq + 2][j] = f2tf32(vv.z);
            v_s[dq + 3][j] = f2tf32(vv.w);
        }
        __syncthreads();

        if (ks > qw + 15 || ks + CK2 - 1 < qw - (WIN_ - 1)) continue;

        float s[4][4];
        #pragma unroll
        for (int nt = 0; nt < 4; nt++)
            #pragma unroll
            for (int r = 0; r < 4; r++) s[nt][r] = 0.f;
        #pragma unroll
        for (int kk = 0; kk < 8; kk++) {
            uint32_t bf[4][2];
            #pragma unroll
            for (int nt = 0; nt < 4; nt++) {
                bf[nt][0] = k_s[nt * 8 + g][kk * 8 + q];
                bf[nt][1] = k_s[nt * 8 + g][kk * 8 + q + 4];
            }
            #pragma unroll
            for (int nt = 0; nt < 4; nt++)
                mma_tf32_16x8x8(s[nt], aq[kk], bf[nt]);
        }

        #pragma unroll
        for (int nt = 0; nt < 4; nt++) {
            const int j0 = ks + nt * 8 + 2 * q;
            const int j1 = j0 + 1;
            s[nt][0] = ((unsigned)(qg0 - j0) < WIN_) ? s[nt][0] : -1e30f;
            s[nt][1] = ((unsigned)(qg0 - j1) < WIN_) ? s[nt][1] : -1e30f;
            s[nt][2] = ((unsigned)(qg1 - j0) < WIN_) ? s[nt][2] : -1e30f;
            s[nt][3] = ((unsigned)(qg1 - j1) < WIN_) ? s[nt][3] : -1e30f;
        }

        float cm0 = -1e30f, cm1 = -1e30f;
        #pragma unroll
        for (int nt = 0; nt < 4; nt++) {
            cm0 = fmaxf(cm0, fmaxf(s[nt][0], s[nt][1]));
            cm1 = fmaxf(cm1, fmaxf(s[nt][2], s[nt][3]));
        }
        cm0 = fmaxf(cm0, __shfl_xor_sync(0xffffffffu, cm0, 1));
        cm0 = fmaxf(cm0, __shfl_xor_sync(0xffffffffu, cm0, 2));
        cm1 = fmaxf(cm1, __shfl_xor_sync(0xffffffffu, cm1, 1));
        cm1 = fmaxf(cm1, __shfl_xor_sync(0xffffffffu, cm1, 2));

        const float m0n = fmaxf(m0r, cm0), m1n = fmaxf(m1r, cm1);
        const float c0  = __expf(m0r - m0n), c1 = __expf(m1r - m1n);

        float p[4][4];
        float ps0 = 0.f, ps1 = 0.f;
        #pragma unroll
        for (int nt = 0; nt < 4; nt++) {
            p[nt][0] = __expf(s[nt][0] - m0n);
            p[nt][1] = __expf(s[nt][1] - m0n);
            p[nt][2] = __expf(s[nt][2] - m1n);
            p[nt][3] = __expf(s[nt][3] - m1n);
            ps0 += p[nt][0] + p[nt][1];
            ps1 += p[nt][2] + p[nt][3];
        }
        ps0 += __shfl_xor_sync(0xffffffffu, ps0, 1);
        ps0 += __shfl_xor_sync(0xffffffffu, ps0, 2);
        ps1 += __shfl_xor_sync(0xffffffffu, ps1, 1);
        ps1 += __shfl_xor_sync(0xffffffffu, ps1, 2);

        l0 = l0 * c0 + ps0;  m0r = m0n;
        l1 = l1 * c1 + ps1;  m1r = m1n;
        #pragma unroll
        for (int dt = 0; dt < 8; dt++) {
            o[dt][0] *= c0;  o[dt][1] *= c0;
            o[dt][2] *= c1;  o[dt][3] *= c1;
        }

        #pragma unroll
        for (int nt = 0; nt < 4; nt++) {
            uint2 u0, u1;
            u0.x = f2tf32(p[nt][0]); u0.y = f2tf32(p[nt][1]);
            u1.x = f2tf32(p[nt][2]); u1.y = f2tf32(p[nt][3]);
            *(uint2*)&p_s[w][g    ][nt * 8 + 2 * q] = u0;
            *(uint2*)&p_s[w][g + 8][nt * 8 + 2 * q] = u1;
        }
        __syncwarp();

        #pragma unroll
        for (int kk = 0; kk < 4; kk++) {
            uint32_t ap[4];
            ap[0] = p_s[w][g    ][kk * 8 + q];
            ap[1] = p_s[w][g + 8][kk * 8 + q];
            ap[2] = p_s[w][g    ][kk * 8 + q + 4];
            ap[3] = p_s[w][g + 8][kk * 8 + q + 4];
            #pragma unroll
            for (int dt = 0; dt < 8; dt++) {
                uint32_t bv[2];
                bv[0] = v_s[dt * 8 + g][kk * 8 + q];
                bv[1] = v_s[dt * 8 + g][kk * 8 + q + 4];
                mma_tf32_16x8x8(o[dt], ap, bv);
            }
        }
    }

    const float i0 = 1.f / l0, i1 = 1.f / l1;
    #pragma unroll
    for (int dt = 0; dt < 8; dt++) {
        const int d = dt * 8 + 2 * q;
        float2 o0; o0.x = o[dt][0] * i0; o0.y = o[dt][1] * i0;
        float2 o1; o1.x = o[dt][2] * i1; o1.y = o[dt][3] * i1;
        *(float2*)&g_att[((long)(b * T_ + qg0)) * C_ + h * D_ + d] = o0;
        *(float2*)&g_att[((long)(b * T_ + qg1)) * C_ + h * D_ + d] = o1;
    }
}

// ---------------------------------------------------------------------------
// Launch. Inputs identified by element count (all distinct). The smem
// attribute is set unconditionally on every call (deterministic; host-side
// call, not a stream op, so graph capture is unaffected).
// ---------------------------------------------------------------------------
extern "C" void kernel_launch(void* const* d_in, const int* in_sizes, int n_in,
                              void* d_out, int out_size)
{
    const float* x      = 0;
    const float* qkv_w  = 0;
    const float* qkv_b  = 0;
    const float* proj_w = 0;
    const float* proj_b = 0;

    for (int i = 0; i < n_in; i++) {
        switch (in_sizes[i]) {
            case B_ * T_ * C_:  x      = (const float*)d_in[i]; break; // 8388608
            case T_ * T_:       /* attn_mask — unused */         break; // 4194304
            case 3 * C_ * C_:   qkv_w  = (const float*)d_in[i]; break; // 3145728
            case 3 * C_:        qkv_b  = (const float*)d_in[i]; break; // 3072
            case C_ * C_:       proj_w = (const float*)d_in[i]; break; // 1048576
            case C_:            proj_b = (const float*)d_in[i]; break; // 1024
        }
    }

    float* out = (float*)d_out;

    cudaFuncSetAttribute(gemm_tf32<1>,
        cudaFuncAttributeMaxDynamicSharedMemorySize, GSMEM_BYTES);
    cudaFuncSetAttribute(gemm_tf32<2>,
        cudaFuncAttributeMaxDynamicSharedMemorySize, GSMEM_BYTES);

    // QKV: [8192,1024] x [3072,1024]^T -> scatter to g_q/g_k/g_v
    {
        dim3 grid(3 * C_ / 128, (B_ * T_) / 128);
        gemm_tf32<1><<<grid, 256, GSMEM_BYTES>>>(x, qkv_w, qkv_b, nullptr,
                                                 B_ * T_, 3 * C_, C_);
    }
    // Attention (tensor-core)
    {
        dim3 grid(T_ / QT, H_, B_);
        attn_mma_kernel<<<grid, 256>>>();
    }
    // Proj: g_att [8192,1024] x [1024,1024]^T -> out
    {
        dim3 grid(C_ / 128, (B_ * T_) / 128);
        gemm_tf32<2><<<grid, 256, GSMEM_BYTES>>>(nullptr, proj_w, proj_b, out,
                                                 B_ * T_, C_, C_);
    }
}

// round 11
// speedup vs baseline: 1.0492x; 1.0492x over previous
#include <cuda_runtime.h>
#include <math.h>
#include <stdint.h>

#define B_    4
#define T_    2048
#define C_    1024
#define H_    16
#define D_    64
#define WIN_  256

// Scratch (device globals; no runtime allocation allowed)
__device__ float g_q[B_*H_*T_*D_];
__device__ float g_k[B_*H_*T_*D_];
__device__ float g_v[B_*H_*T_*D_];
__device__ __align__(16) float g_att[B_*T_*C_];
// Pre-rounded (tf32-in-fp32-bits) operand copies
__device__ __align__(16) float g_xr[B_*T_*C_];
__device__ __align__(16) float g_wqkv[3*C_*C_];
__device__ __align__(16) float g_wproj[C_*C_];

__device__ __forceinline__ uint32_t f2tf32(float x) {
    uint32_t r;
    asm("cvt.rna.tf32.f32 %0, %1;" : "=r"(r) : "f"(x));
    return r;
}

__device__ __forceinline__ void mma_tf32_16x8x8(
    float* d, const uint32_t* a, const uint32_t* b)
{
    asm volatile(
        "mma.sync.aligned.m16n8k8.row.col.f32.tf32.tf32.f32 "
        "{%0,%1,%2,%3}, {%4,%5,%6,%7}, {%8,%9}, {%0,%1,%2,%3};"
        : "+f"(d[0]), "+f"(d[1]), "+f"(d[2]), "+f"(d[3])
        : "r"(a[0]), "r"(a[1]), "r"(a[2]), "r"(a[3]),
          "r"(b[0]), "r"(b[1]));
}

__device__ __forceinline__ uint32_t smem_u32(const void* p) {
    uint32_t a;
    asm("{ .reg .u64 t; cvta.to.shared.u64 t, %1; cvt.u32.u64 %0, t; }"
        : "=r"(a) : "l"(p));
    return a;
}

__device__ __forceinline__ void cp16(uint32_t s, const void* g) {
    asm volatile("cp.async.cg.shared.global [%0], [%1], 16;"
                 :: "r"(s), "l"(g));
}
#define CP_COMMIT() asm volatile("cp.async.commit_group;" ::: "memory")
#define CP_WAIT(n)  asm volatile("cp.async.wait_group %0;" :: "n"(n) : "memory")

// ---------------------------------------------------------------------------
// Prepass: round fp32 -> tf32 bits in gmem (once per launch, ~25us total).
// SEL 0: g_xr <- x ; 1: g_wqkv <- qkv_w ; 2: g_wproj <- proj_w
// ---------------------------------------------------------------------------
template<int SEL>
__global__ void round_tf32(const float4* __restrict__ src, int n4)
{
    float4* dst = (SEL == 0) ? (float4*)g_xr
                : (SEL == 1) ? (float4*)g_wqkv : (float4*)g_wproj;
    for (int i = blockIdx.x * blockDim.x + threadIdx.x; i < n4;
         i += gridDim.x * blockDim.x) {
        float4 v = src[i];
        v.x = __uint_as_float(f2tf32(v.x));
        v.y = __uint_as_float(f2tf32(v.y));
        v.z = __uint_as_float(f2tf32(v.z));
        v.w = __uint_as_float(f2tf32(v.w));
        dst[i] = v;
    }
}

// ---------------------------------------------------------------------------
// tf32 tensor-core GEMM, NT: C[m,n] = sum_k A[m,k]*Bw[n,k] + bias[n]
// Operands are PRE-ROUNDED tf32 bits in gmem; staged via cp.async (zero
// staging registers, no spills, no in-loop cvt). 2-stage pipeline:
//   issue chunk c+1; wait_group<1>; sync; mma(buf c); sync.
// Block tile 128x128x32, 256 threads, warp tile 64x32, smem [m][k] KPAD 36
// (coalesced gmem, conflict-free fragment LDS banks 4g+q).
// MODE 1: A=g_xr, B=g_wqkv, qkv scatter. MODE 2: A=g_att, B=g_wproj.
// (All device-global operands bound in device code — host-passed __device__
//  symbols silently read the host shadow via ATS.)
// ---------------------------------------------------------------------------
#define KPAD 36
#define BUFW (2 * 128 * KPAD)
#define GSMEM_BYTES (2 * BUFW * 4)   // 73728 B

template<int MODE>
__global__ __launch_bounds__(256, 2) void gemm_cp(
    const float* __restrict__ bias,
    float* __restrict__ Cout,
    int M, int N, int K)
{
    extern __shared__ uint32_t sm[];
    const uint32_t sbase = smem_u32(sm);

    const float* __restrict__ A  = (MODE == 1) ? g_xr   : (const float*)g_att;
    const float* __restrict__ Bw = (MODE == 1) ? g_wqkv : g_wproj;

    const int tid  = threadIdx.x;
    const int w    = tid >> 5;
    const int lane = tid & 31;
    const int gid  = lane >> 2;
    const int qid  = lane & 3;
    const int wm   = w & 1;
    const int wn   = w >> 1;
    const int m0   = blockIdx.y * 128;
    const int n0   = blockIdx.x * 128;

    // copy map: f = tid + it*256 -> row = f>>3, k4 = (f&7)*4 (coalesced)
    int srow[4], sk4[4];
    #pragma unroll
    for (int it = 0; it < 4; it++) {
        int f = tid + it * 256;
        srow[it] = f >> 3;
        sk4[it]  = (f & 7) << 2;
    }

    float acc[4][4][4];
    #pragma unroll
    for (int i = 0; i < 4; i++)
        #pragma unroll
        for (int j = 0; j < 4; j++)
            #pragma unroll
            for (int r = 0; r < 4; r++) acc[i][j][r] = 0.f;

    const int nch = K / 32;

    // Issue chunk 0 into buffer 0
    {
        const uint32_t as0 = sbase;
        const uint32_t bs0 = sbase + 128 * KPAD * 4;
        #pragma unroll
        for (int it = 0; it < 4; it++) {
            const uint32_t so = (uint32_t)(srow[it] * KPAD + sk4[it]) * 4;
            cp16(as0 + so, &A [(long)(m0 + srow[it]) * K + sk4[it]]);
            cp16(bs0 + so, &Bw[(long)(n0 + srow[it]) * K + sk4[it]]);
        }
        CP_COMMIT();
    }

    for (int c = 0; c < nch; c++) {
        // Issue chunk c+1 into the other buffer, then wait for chunk c
        if (c + 1 < nch) {
            const int k0 = (c + 1) * 32;
            const uint32_t an = sbase + ((c + 1) & 1) * BUFW * 4;
            const uint32_t bn = an + 128 * KPAD * 4;
            #pragma unroll
            for (int it = 0; it < 4; it++) {
                const uint32_t so = (uint32_t)(srow[it] * KPAD + sk4[it]) * 4;
                cp16(an + so, &A [(long)(m0 + srow[it]) * K + k0 + sk4[it]]);
                cp16(bn + so, &Bw[(long)(n0 + srow[it]) * K + k0 + sk4[it]]);
            }
            CP_COMMIT();
            CP_WAIT(1);
        } else {
            CP_WAIT(0);
        }
        __syncthreads();

        const uint32_t* As = sm + (c & 1) * BUFW;
        const uint32_t* Bs = As + 128 * KPAD;

        #pragma unroll
        for (int kk = 0; kk < 4; kk++) {
            const int kb = kk * 8;
            uint32_t af[4][4], bf[4][2];
            #pragma unroll
            for (int im = 0; im < 4; im++) {
                const int mr = wm * 64 + im * 16 + gid;
                af[im][0] = As[ mr      * KPAD + kb + qid];
                af[im][1] = As[(mr + 8) * KPAD + kb + qid];
                af[im][2] = As[ mr      * KPAD + kb + qid + 4];
                af[im][3] = As[(mr + 8) * KPAD + kb + qid + 4];
            }
            #pragma unroll
            for (int in = 0; in < 4; in++) {
                const int nc = wn * 32 + in * 8 + gid;
                bf[in][0] = Bs[nc * KPAD + kb + qid];
                bf[in][1] = Bs[nc * KPAD + kb + qid + 4];
            }
            #pragma unroll
            for (int im = 0; im < 4; im++)
                #pragma unroll
                for (int in = 0; in < 4; in++)
                    mma_tf32_16x8x8(acc[im][in], af[im], bf[in]);
        }
        __syncthreads();
    }

    // Epilogue: c0:(gid,2q) c1:(gid,2q+1) c2:(gid+8,2q) c3:(gid+8,2q+1)
    #pragma unroll
    for (int im = 0; im < 4; im++) {
        #pragma unroll
        for (int in = 0; in < 4; in++) {
            const int mbase = m0 + wm * 64 + im * 16 + gid;
            const int nbase = n0 + wn * 32 + in * 8 + qid * 2;
            #pragma unroll
            for (int r = 0; r < 4; r++) {
                const int m = mbase + (r >> 1) * 8;
                const int n = nbase + (r & 1);
                float v = acc[im][in][r] + bias[n];
                if (MODE == 1) {
                    int s = n >> 10;
                    int h = (n >> 6) & 15;
                    int d = n & 63;
                    int b = m >> 11;
                    int t = m & 2047;
                    float* dst = (s == 0) ? g_q : (s == 1 ? g_k : g_v);
                    dst[(((long)(b * H_ + h)) * T_ + t) * D_ + d] = v;
                } else {
                    Cout[(long)m * N + n] = v;
                }
            }
        }
    }
}

// ---------------------------------------------------------------------------
// Tensor-core windowed attention (R8 structure). Epilogue now stores g_att
// PRE-ROUNDED to tf32 bits so the proj GEMM can consume it directly.
// ---------------------------------------------------------------------------
#define QT  128
#define CK2 32

__global__ __launch_bounds__(256, 2) void attn_mma_kernel()
{
    __shared__ uint32_t k_s[CK2][68];
    __shared__ uint32_t v_s[64][40];
    __shared__ uint32_t p_s[8][16][40];

    const int tid  = threadIdx.x;
    const int w    = tid >> 5;
    const int lane = tid & 31;
    const int g    = lane >> 2;
    const int q    = lane & 3;
    const int q0   = blockIdx.x * QT;
    const int h    = blockIdx.y;
    const int b    = blockIdx.z;

    const long bh   = (long)(b * H_ + h);
    const float* Qp = g_q + bh * T_ * D_;
    const float* Kp = g_k + bh * T_ * D_;
    const float* Vp = g_v + bh * T_ * D_;

    const int qw  = q0 + w * 16;
    const int qg0 = qw + g;
    const int qg1 = qw + g + 8;

    uint32_t aq[8][4];
    #pragma unroll
    for (int kk = 0; kk < 8; kk++) {
        aq[kk][0] = f2tf32(Qp[(long)qg0 * D_ + kk * 8 + q    ] * 0.125f);
        aq[kk][1] = f2tf32(Qp[(long)qg1 * D_ + kk * 8 + q    ] * 0.125f);
        aq[kk][2] = f2tf32(Qp[(long)qg0 * D_ + kk * 8 + q + 4] * 0.125f);
        aq[kk][3] = f2tf32(Qp[(long)qg1 * D_ + kk * 8 + q + 4] * 0.125f);
    }

    int lo_blk = q0 - (WIN_ - 1);
    if (lo_blk < 0) lo_blk = 0;
    lo_blk &= ~(CK2 - 1);
    const int nchunks = ((q0 + QT - 1) - lo_blk) / CK2 + 1;

    float o[8][4];
    #pragma unroll
    for (int dt = 0; dt < 8; dt++)
        #pragma unroll
        for (int r = 0; r < 4; r++) o[dt][r] = 0.f;
    float m0r = -1e30f, m1r = -1e30f, l0 = 0.f, l1 = 0.f;

    for (int c = 0; c < nchunks; c++) {
        const int ks = lo_blk + c * CK2;
        __syncthreads();
        #pragma unroll
        for (int it = 0; it < 2; it++) {
            int f    = tid + it * 256;
            int j    = f >> 4;
            int qd   = (f & 15) << 2;
            float4 kv = *(const float4*)&Kp[(long)(ks + j) * D_ + qd];
            uint4 uk;
            uk.x = f2tf32(kv.x); uk.y = f2tf32(kv.y);
            uk.z = f2tf32(kv.z); uk.w = f2tf32(kv.w);
            *(uint4*)&k_s[j][qd] = uk;
        }
        #pragma unroll
        for (int it = 0; it < 2; it++) {
            int f   = tid + it * 256;
            int j   = f & 31;
            int dq  = (f >> 5) << 2;
            float4 vv = *(const float4*)&Vp[(long)(ks + j) * D_ + dq];
            v_s[dq + 0][j] = f2tf32(vv.x);
            v_s[dq + 1][j] = f2tf32(vv.y);
            v_s[dq + 2][j] = f2tf32(vv.z);
            v_s[dq + 3][j] = f2tf32(vv.w);
        }
        __syncthreads();

        if (ks > qw + 15 || ks + CK2 - 1 < qw - (WIN_ - 1)) continue;

        float s[4][4];
        #pragma unroll
        for (int nt = 0; nt < 4; nt++)
            #pragma unroll
            for (int r = 0; r < 4; r++) s[nt][r] = 0.f;
        #pragma unroll
        for (int kk = 0; kk < 8; kk++) {
            uint32_t bf[4][2];
            #pragma unroll
            for (int nt = 0; nt < 4; nt++) {
                bf[nt][0] = k_s[nt * 8 + g][kk * 8 + q];
                bf[nt][1] = k_s[nt * 8 + g][kk * 8 + q + 4];
            }
            #pragma unroll
            for (int nt = 0; nt < 4; nt++)
                mma_tf32_16x8x8(s[nt], aq[kk], bf[nt]);
        }

        #pragma unroll
        for (int nt = 0; nt < 4; nt++) {
            const int j0 = ks + nt * 8 + 2 * q;
            const int j1 = j0 + 1;
            s[nt][0] = ((unsigned)(qg0 - j0) < WIN_) ? s[nt][0] : -1e30f;
            s[nt][1] = ((unsigned)(qg0 - j1) < WIN_) ? s[nt][1] : -1e30f;
            s[nt][2] = ((unsigned)(qg1 - j0) < WIN_) ? s[nt][2] : -1e30f;
            s[nt][3] = ((unsigned)(qg1 - j1) < WIN_) ? s[nt][3] : -1e30f;
        }

        float cm0 = -1e30f, cm1 = -1e30f;
        #pragma unroll
        for (int nt = 0; nt < 4; nt++) {
            cm0 = fmaxf(cm0, fmaxf(s[nt][0], s[nt][1]));
            cm1 = fmaxf(cm1, fmaxf(s[nt][2], s[nt][3]));
        }
        cm0 = fmaxf(cm0, __shfl_xor_sync(0xffffffffu, cm0, 1));
        cm0 = fmaxf(cm0, __shfl_xor_sync(0xffffffffu, cm0, 2));
        cm1 = fmaxf(cm1, __shfl_xor_sync(0xffffffffu, cm1, 1));
        cm1 = fmaxf(cm1, __shfl_xor_sync(0xffffffffu, cm1, 2));

        const float m0n = fmaxf(m0r, cm0), m1n = fmaxf(m1r, cm1);
        const float c0  = __expf(m0r - m0n), c1 = __expf(m1r - m1n);

        float p[4][4];
        float ps0 = 0.f, ps1 = 0.f;
        #pragma unroll
        for (int nt = 0; nt < 4; nt++) {
            p[nt][0] = __expf(s[nt][0] - m0n);
            p[nt][1] = __expf(s[nt][1] - m0n);
            p[nt][2] = __expf(s[nt][2] - m1n);
            p[nt][3] = __expf(s[nt][3] - m1n);
            ps0 += p[nt][0] + p[nt][1];
            ps1 += p[nt][2] + p[nt][3];
        }
        ps0 += __shfl_xor_sync(0xffffffffu, ps0, 1);
        ps0 += __shfl_xor_sync(0xffffffffu, ps0, 2);
        ps1 += __shfl_xor_sync(0xffffffffu, ps1, 1);
        ps1 += __shfl_xor_sync(0xffffffffu, ps1, 2);

        l0 = l0 * c0 + ps0;  m0r = m0n;
        l1 = l1 * c1 + ps1;  m1r = m1n;
        #pragma unroll
        for (int dt = 0; dt < 8; dt++) {
            o[dt][0] *= c0;  o[dt][1] *= c0;
            o[dt][2] *= c1;  o[dt][3] *= c1;
        }

        #pragma unroll
        for (int nt = 0; nt < 4; nt++) {
            uint2 u0, u1;
            u0.x = f2tf32(p[nt][0]); u0.y = f2tf32(p[nt][1]);
            u1.x = f2tf32(p[nt][2]); u1.y = f2tf32(p[nt][3]);
            *(uint2*)&p_s[w][g    ][nt * 8 + 2 * q] = u0;
            *(uint2*)&p_s[w][g + 8][nt * 8 + 2 * q] = u1;
        }
        __syncwarp();

        #pragma unroll
        for (int kk = 0; kk < 4; kk++) {
            uint32_t ap[4];
            ap[0] = p_s[w][g    ][kk * 8 + q];
            ap[1] = p_s[w][g + 8][kk * 8 + q];
            ap[2] = p_s[w][g    ][kk * 8 + q + 4];
            ap[3] = p_s[w][g + 8][kk * 8 + q + 4];
            #pragma unroll
            for (int dt = 0; dt < 8; dt++) {
                uint32_t bv[2];
                bv[0] = v_s[dt * 8 + g][kk * 8 + q];
                bv[1] = v_s[dt * 8 + g][kk * 8 + q + 4];
                mma_tf32_16x8x8(o[dt], ap, bv);
            }
        }
    }

    // Epilogue: store PRE-ROUNDED tf32 bits (proj GEMM consumes directly)
    const float i0 = 1.f / l0, i1 = 1.f / l1;
    #pragma unroll
    for (int dt = 0; dt < 8; dt++) {
        const int d = dt * 8 + 2 * q;
        float2 o0, o1;
        o0.x = __uint_as_float(f2tf32(o[dt][0] * i0));
        o0.y = __uint_as_float(f2tf32(o[dt][1] * i0));
        o1.x = __uint_as_float(f2tf32(o[dt][2] * i1));
        o1.y = __uint_as_float(f2tf32(o[dt][3] * i1));
        *(float2*)&g_att[((long)(b * T_ + qg0)) * C_ + h * D_ + d] = o0;
        *(float2*)&g_att[((long)(b * T_ + qg1)) * C_ + h * D_ + d] = o1;
    }
}

// ---------------------------------------------------------------------------
// Launch. Inputs identified by element count (all distinct).
// ---------------------------------------------------------------------------
extern "C" void kernel_launch(void* const* d_in, const int* in_sizes, int n_in,
                              void* d_out, int out_size)
{
    const float* x      = 0;
    const float* qkv_w  = 0;
    const float* qkv_b  = 0;
    const float* proj_w = 0;
    const float* proj_b = 0;

    for (int i = 0; i < n_in; i++) {
        switch (in_sizes[i]) {
            case B_ * T_ * C_:  x      = (const float*)d_in[i]; break; // 8388608
            case T_ * T_:       /* attn_mask — unused */         break; // 4194304
            case 3 * C_ * C_:   qkv_w  = (const float*)d_in[i]; break; // 3145728
            case 3 * C_:        qkv_b  = (const float*)d_in[i]; break; // 3072
            case C_ * C_:       proj_w = (const float*)d_in[i]; break; // 1048576
            case C_:            proj_b = (const float*)d_in[i]; break; // 1024
        }
    }

    float* out = (float*)d_out;

    cudaFuncSetAttribute(gemm_cp<1>,
        cudaFuncAttributeMaxDynamicSharedMemorySize, GSMEM_BYTES);
    cudaFuncSetAttribute(gemm_cp<2>,
        cudaFuncAttributeMaxDynamicSharedMemorySize, GSMEM_BYTES);

    // Prepass: round operands to tf32 bits in gmem
    round_tf32<0><<<2048, 256>>>((const float4*)x,      (B_*T_*C_) / 4);
    round_tf32<1><<<1024, 256>>>((const float4*)qkv_w,  (3*C_*C_) / 4);
    round_tf32<2><<<512,  256>>>((const float4*)proj_w, (C_*C_) / 4);

    // QKV: g_xr [8192,1024] x g_wqkv [3072,1024]^T -> scatter q/k/v
    {
        dim3 grid(3 * C_ / 128, (B_ * T_) / 128);
        gemm_cp<1><<<grid, 256, GSMEM_BYTES>>>(qkv_b, nullptr,
                                               B_ * T_, 3 * C_, C_);
    }
    // Attention (tensor-core)
    {
        dim3 grid(T_ / QT, H_, B_);
        attn_mma_kernel<<<grid, 256>>>();
    }
    // Proj: g_att [8192,1024] x g_wproj [1024,1024]^T -> out
    {
        dim3 grid(C_ / 128, (B_ * T_) / 128);
        gemm_cp<2><<<grid, 256, GSMEM_BYTES>>>(proj_b, out,
                                               B_ * T_, C_, C_);
    }
}

// round 12
// speedup vs baseline: 1.0672x; 1.0172x over previous
#include <cuda_runtime.h>
#include <math.h>
#include <stdint.h>

#define B_    4
#define T_    2048
#define C_    1024
#define H_    16
#define D_    64
#define WIN_  256

// Scratch (device globals; no runtime allocation allowed)
__device__ float g_q[B_*H_*T_*D_];
__device__ float g_k[B_*H_*T_*D_];
__device__ float g_v[B_*H_*T_*D_];
__device__ __align__(16) float g_att[B_*T_*C_];
// Pre-rounded (tf32-in-fp32-bits) operand copies
__device__ __align__(16) float g_xr[B_*T_*C_];
__device__ __align__(16) float g_wqkv[3*C_*C_];
__device__ __align__(16) float g_wproj[C_*C_];

__device__ __forceinline__ uint32_t f2tf32(float x) {
    uint32_t r;
    asm("cvt.rna.tf32.f32 %0, %1;" : "=r"(r) : "f"(x));
    return r;
}

__device__ __forceinline__ void mma_tf32_16x8x8(
    float* d, const uint32_t* a, const uint32_t* b)
{
    asm volatile(
        "mma.sync.aligned.m16n8k8.row.col.f32.tf32.tf32.f32 "
        "{%0,%1,%2,%3}, {%4,%5,%6,%7}, {%8,%9}, {%0,%1,%2,%3};"
        : "+f"(d[0]), "+f"(d[1]), "+f"(d[2]), "+f"(d[3])
        : "r"(a[0]), "r"(a[1]), "r"(a[2]), "r"(a[3]),
          "r"(b[0]), "r"(b[1]));
}

__device__ __forceinline__ uint32_t smem_u32(const void* p) {
    uint32_t a;
    asm("{ .reg .u64 t; cvta.to.shared.u64 t, %1; cvt.u32.u64 %0, t; }"
        : "=r"(a) : "l"(p));
    return a;
}

__device__ __forceinline__ void cp16(uint32_t s, const void* g) {
    asm volatile("cp.async.cg.shared.global [%0], [%1], 16;"
                 :: "r"(s), "l"(g));
}
#define CP_COMMIT() asm volatile("cp.async.commit_group;" ::: "memory")
#define CP_WAIT(n)  asm volatile("cp.async.wait_group %0;" :: "n"(n) : "memory")

// ---------------------------------------------------------------------------
// Prepass: round fp32 -> tf32 bits in gmem.
// SEL 0: g_xr <- x ; 1: g_wqkv <- qkv_w ; 2: g_wproj <- proj_w
// ---------------------------------------------------------------------------
template<int SEL>
__global__ void round_tf32(const float4* __restrict__ src, int n4)
{
    float4* dst = (SEL == 0) ? (float4*)g_xr
                : (SEL == 1) ? (float4*)g_wqkv : (float4*)g_wproj;
    for (int i = blockIdx.x * blockDim.x + threadIdx.x; i < n4;
         i += gridDim.x * blockDim.x) {
        float4 v = src[i];
        v.x = __uint_as_float(f2tf32(v.x));
        v.y = __uint_as_float(f2tf32(v.y));
        v.z = __uint_as_float(f2tf32(v.z));
        v.w = __uint_as_float(f2tf32(v.w));
        dst[i] = v;
    }
}

// ---------------------------------------------------------------------------
// tf32 tensor-core GEMM, NT: C[m,n] = sum_k A[m,k]*Bw[n,k] + bias[n]
// 128-thread CTA (4 warps), CTA tile 128x128x32, WARP TILE 64x64
// (4x8 grid of m16n8k8): LDS/mma ratio 1.0 (was 1.5 at 64x32).
// Pre-rounded operands; cp.async double-buffered staging; KPAD 36 keeps
// fragment LDS conflict-free (banks 4g+q all distinct).
// __launch_bounds__(128, 2): 256 regs available, acc=128 + frags fits.
// MODE 1: A=g_xr, B=g_wqkv, qkv scatter. MODE 2: A=g_att, B=g_wproj.
// ---------------------------------------------------------------------------
#define KPAD 36
#define BUFW (2 * 128 * KPAD)
#define GSMEM_BYTES (2 * BUFW * 4)   // 73728 B

template<int MODE>
__global__ __launch_bounds__(128, 2) void gemm_cp(
    const float* __restrict__ bias,
    float* __restrict__ Cout,
    int M, int N, int K)
{
    extern __shared__ uint32_t sm[];
    const uint32_t sbase = smem_u32(sm);

    const float* __restrict__ A  = (MODE == 1) ? g_xr   : (const float*)g_att;
    const float* __restrict__ Bw = (MODE == 1) ? g_wqkv : g_wproj;

    const int tid  = threadIdx.x;
    const int w    = tid >> 5;
    const int lane = tid & 31;
    const int g    = lane >> 2;   // 0..7
    const int q    = lane & 3;    // 0..3
    const int wm   = w & 1;       // 2 warp-rows of 64
    const int wn   = w >> 1;      // 2 warp-cols of 64
    const int m0   = blockIdx.y * 128;
    const int n0   = blockIdx.x * 128;

    float acc[4][8][4];
    #pragma unroll
    for (int i = 0; i < 4; i++)
        #pragma unroll
        for (int j = 0; j < 8; j++)
            #pragma unroll
            for (int r = 0; r < 4; r++) acc[i][j][r] = 0.f;

    const int nch = K / 32;

    // Issue chunk 0 into buffer 0 (8 cp16 per matrix per thread)
    {
        const uint32_t as0 = sbase;
        const uint32_t bs0 = sbase + 128 * KPAD * 4;
        #pragma unroll
        for (int it = 0; it < 8; it++) {
            int f   = tid + it * 128;
            int row = f >> 3;
            int k4  = (f & 7) << 2;
            const uint32_t so = (uint32_t)(row * KPAD + k4) * 4;
            cp16(as0 + so, &A [(long)(m0 + row) * K + k4]);
            cp16(bs0 + so, &Bw[(long)(n0 + row) * K + k4]);
        }
        CP_COMMIT();
    }

    for (int c = 0; c < nch; c++) {
        // Issue chunk c+1 into the other buffer, then wait for chunk c
        if (c + 1 < nch) {
            const int k0 = (c + 1) * 32;
            const uint32_t an = sbase + ((c + 1) & 1) * BUFW * 4;
            const uint32_t bn = an + 128 * KPAD * 4;
            #pragma unroll
            for (int it = 0; it < 8; it++) {
                int f   = tid + it * 128;
                int row = f >> 3;
                int k4  = (f & 7) << 2;
                const uint32_t so = (uint32_t)(row * KPAD + k4) * 4;
                cp16(an + so, &A [(long)(m0 + row) * K + k0 + k4]);
                cp16(bn + so, &Bw[(long)(n0 + row) * K + k0 + k4]);
            }
            CP_COMMIT();
            CP_WAIT(1);
        } else {
            CP_WAIT(0);
        }
        __syncthreads();

        const uint32_t* As = sm + (c & 1) * BUFW;
        const uint32_t* Bs = As + 128 * KPAD;

        #pragma unroll
        for (int kk = 0; kk < 4; kk++) {
            const int kb = kk * 8;
            uint32_t af[4][4], bf[8][2];
            #pragma unroll
            for (int im = 0; im < 4; im++) {
                const int mr = wm * 64 + im * 16 + g;
                af[im][0] = As[ mr      * KPAD + kb + q];
                af[im][1] = As[(mr + 8) * KPAD + kb + q];
                af[im][2] = As[ mr      * KPAD + kb + q + 4];
                af[im][3] = As[(mr + 8) * KPAD + kb + q + 4];
            }
            #pragma unroll
            for (int in = 0; in < 8; in++) {
                const int nc = wn * 64 + in * 8 + g;
                bf[in][0] = Bs[nc * KPAD + kb + q];
                bf[in][1] = Bs[nc * KPAD + kb + q + 4];
            }
            #pragma unroll
            for (int im = 0; im < 4; im++)
                #pragma unroll
                for (int in = 0; in < 8; in++)
                    mma_tf32_16x8x8(acc[im][in], af[im], bf[in]);
        }
        __syncthreads();
    }

    // Epilogue: c0:(g,2q) c1:(g,2q+1) c2:(g+8,2q) c3:(g+8,2q+1)
    #pragma unroll
    for (int im = 0; im < 4; im++) {
        #pragma unroll
        for (int in = 0; in < 8; in++) {
            const int mbase = m0 + wm * 64 + im * 16 + g;
            const int nbase = n0 + wn * 64 + in * 8 + q * 2;
            #pragma unroll
            for (int r = 0; r < 4; r++) {
                const int m = mbase + (r >> 1) * 8;
                const int n = nbase + (r & 1);
                float v = acc[im][in][r] + bias[n];
                if (MODE == 1) {
                    int s = n >> 10;
                    int h = (n >> 6) & 15;
                    int d = n & 63;
                    int b = m >> 11;
                    int t = m & 2047;
                    float* dst = (s == 0) ? g_q : (s == 1 ? g_k : g_v);
                    dst[(((long)(b * H_ + h)) * T_ + t) * D_ + d] = v;
                } else {
                    Cout[(long)m * N + n] = v;
                }
            }
        }
    }
}

// ---------------------------------------------------------------------------
// Tensor-core windowed attention (unchanged from R11). Epilogue stores
// g_att pre-rounded to tf32 bits for the proj GEMM.
// ---------------------------------------------------------------------------
#define QT  128
#define CK2 32

__global__ __launch_bounds__(256, 2) void attn_mma_kernel()
{
    __shared__ uint32_t k_s[CK2][68];
    __shared__ uint32_t v_s[64][40];
    __shared__ uint32_t p_s[8][16][40];

    const int tid  = threadIdx.x;
    const int w    = tid >> 5;
    const int lane = tid & 31;
    const int g    = lane >> 2;
    const int q    = lane & 3;
    const int q0   = blockIdx.x * QT;
    const int h    = blockIdx.y;
    const int b    = blockIdx.z;

    const long bh   = (long)(b * H_ + h);
    const float* Qp = g_q + bh * T_ * D_;
    const float* Kp = g_k + bh * T_ * D_;
    const float* Vp = g_v + bh * T_ * D_;

    const int qw  = q0 + w * 16;
    const int qg0 = qw + g;
    const int qg1 = qw + g + 8;

    uint32_t aq[8][4];
    #pragma unroll
    for (int kk = 0; kk < 8; kk++) {
        aq[kk][0] = f2tf32(Qp[(long)qg0 * D_ + kk * 8 + q    ] * 0.125f);
        aq[kk][1] = f2tf32(Qp[(long)qg1 * D_ + kk * 8 + q    ] * 0.125f);
        aq[kk][2] = f2tf32(Qp[(long)qg0 * D_ + kk * 8 + q + 4] * 0.125f);
        aq[kk][3] = f2tf32(Qp[(long)qg1 * D_ + kk * 8 + q + 4] * 0.125f);
    }

    int lo_blk = q0 - (WIN_ - 1);
    if (lo_blk < 0) lo_blk = 0;
    lo_blk &= ~(CK2 - 1);
    const int nchunks = ((q0 + QT - 1) - lo_blk) / CK2 + 1;

    float o[8][4];
    #pragma unroll
    for (int dt = 0; dt < 8; dt++)
        #pragma unroll
        for (int r = 0; r < 4; r++) o[dt][r] = 0.f;
    float m0r = -1e30f, m1r = -1e30f, l0 = 0.f, l1 = 0.f;

    for (int c = 0; c < nchunks; c++) {
        const int ks = lo_blk + c * CK2;
        __syncthreads();
        #pragma unroll
        for (int it = 0; it < 2; it++) {
            int f    = tid + it * 256;
            int j    = f >> 4;
            int qd   = (f & 15) << 2;
            float4 kv = *(const float4*)&Kp[(long)(ks + j) * D_ + qd];
            uint4 uk;
            uk.x = f2tf32(kv.x); uk.y = f2tf32(kv.y);
            uk.z = f2tf32(kv.z); uk.w = f2tf32(kv.w);
            *(uint4*)&k_s[j][qd] = uk;
        }
        #pragma unroll
        for (int it = 0; it < 2; it++) {
            int f   = tid + it * 256;
            int j   = f & 31;
            int dq  = (f >> 5) << 2;
            float4 vv = *(const float4*)&Vp[(long)(ks + j) * D_ + dq];
            v_s[dq + 0][j] = f2tf32(vv.x);
            v_s[dq + 1][j] = f2tf32(vv.y);
            v_s[dq + 2][j] = f2tf32(vv.z);
            v_s[dq + 3][j] = f2tf32(vv.w);
        }
        __syncthreads();

        if (ks > qw + 15 || ks + CK2 - 1 < qw - (WIN_ - 1)) continue;

        float s[4][4];
        #pragma unroll
        for (int nt = 0; nt < 4; nt++)
            #pragma unroll
            for (int r = 0; r < 4; r++) s[nt][r] = 0.f;
        #pragma unroll
        for (int kk = 0; kk < 8; kk++) {
            uint32_t bf[4][2];
            #pragma unroll
            for (int nt = 0; nt < 4; nt++) {
                bf[nt][0] = k_s[nt * 8 + g][kk * 8 + q];
                bf[nt][1] = k_s[nt * 8 + g][kk * 8 + q + 4];
            }
            #pragma unroll
            for (int nt = 0; nt < 4; nt++)
                mma_tf32_16x8x8(s[nt], aq[kk], bf[nt]);
        }

        #pragma unroll
        for (int nt = 0; nt < 4; nt++) {
            const int j0 = ks + nt * 8 + 2 * q;
            const int j1 = j0 + 1;
            s[nt][0] = ((unsigned)(qg0 - j0) < WIN_) ? s[nt][0] : -1e30f;
            s[nt][1] = ((unsigned)(qg0 - j1) < WIN_) ? s[nt][1] : -1e30f;
            s[nt][2] = ((unsigned)(qg1 - j0) < WIN_) ? s[nt][2] : -1e30f;
            s[nt][3] = ((unsigned)(qg1 - j1) < WIN_) ? s[nt][3] : -1e30f;
        }

        float cm0 = -1e30f, cm1 = -1e30f;
        #pragma unroll
        for (int nt = 0; nt < 4; nt++) {
            cm0 = fmaxf(cm0, fmaxf(s[nt][0], s[nt][1]));
            cm1 = fmaxf(cm1, fmaxf(s[nt][2], s[nt][3]));
        }
        cm0 = fmaxf(cm0, __shfl_xor_sync(0xffffffffu, cm0, 1));
        cm0 = fmaxf(cm0, __shfl_xor_sync(0xffffffffu, cm0, 2));
        cm1 = fmaxf(cm1, __shfl_xor_sync(0xffffffffu, cm1, 1));
        cm1 = fmaxf(cm1, __shfl_xor_sync(0xffffffffu, cm1, 2));

        const float m0n = fmaxf(m0r, cm0), m1n = fmaxf(m1r, cm1);
        const float c0  = __expf(m0r - m0n), c1 = __expf(m1r - m1n);

        float p[4][4];
        float ps0 = 0.f, ps1 = 0.f;
        #pragma unroll
        for (int nt = 0; nt < 4; nt++) {
            p[nt][0] = __expf(s[nt][0] - m0n);
            p[nt][1] = __expf(s[nt][1] - m0n);
            p[nt][2] = __expf(s[nt][2] - m1n);
            p[nt][3] = __expf(s[nt][3] - m1n);
            ps0 += p[nt][0] + p[nt][1];
            ps1 += p[nt][2] + p[nt][3];
        }
        ps0 += __shfl_xor_sync(0xffffffffu, ps0, 1);
        ps0 += __shfl_xor_sync(0xffffffffu, ps0, 2);
        ps1 += __shfl_xor_sync(0xffffffffu, ps1, 1);
        ps1 += __shfl_xor_sync(0xffffffffu, ps1, 2);

        l0 = l0 * c0 + ps0;  m0r = m0n;
        l1 = l1 * c1 + ps1;  m1r = m1n;
        #pragma unroll
        for (int dt = 0; dt < 8; dt++) {
            o[dt][0] *= c0;  o[dt][1] *= c0;
            o[dt][2] *= c1;  o[dt][3] *= c1;
        }

        #pragma unroll
        for (int nt = 0; nt < 4; nt++) {
            uint2 u0, u1;
            u0.x = f2tf32(p[nt][0]); u0.y = f2tf32(p[nt][1]);
            u1.x = f2tf32(p[nt][2]); u1.y = f2tf32(p[nt][3]);
            *(uint2*)&p_s[w][g    ][nt * 8 + 2 * q] = u0;
            *(uint2*)&p_s[w][g + 8][nt * 8 + 2 * q] = u1;
        }
        __syncwarp();

        #pragma unroll
        for (int kk = 0; kk < 4; kk++) {
            uint32_t ap[4];
            ap[0] = p_s[w][g    ][kk * 8 + q];
            ap[1] = p_s[w][g + 8][kk * 8 + q];
            ap[2] = p_s[w][g    ][kk * 8 + q + 4];
            ap[3] = p_s[w][g + 8][kk * 8 + q + 4];
            #pragma unroll
            for (int dt = 0; dt < 8; dt++) {
                uint32_t bv[2];
                bv[0] = v_s[dt * 8 + g][kk * 8 + q];
                bv[1] = v_s[dt * 8 + g][kk * 8 + q + 4];
                mma_tf32_16x8x8(o[dt], ap, bv);
            }
        }
    }

    // Epilogue: store PRE-ROUNDED tf32 bits (proj GEMM consumes directly)
    const float i0 = 1.f / l0, i1 = 1.f / l1;
    #pragma unroll
    for (int dt = 0; dt < 8; dt++) {
        const int d = dt * 8 + 2 * q;
        float2 o0, o1;
        o0.x = __uint_as_float(f2tf32(o[dt][0] * i0));
        o0.y = __uint_as_float(f2tf32(o[dt][1] * i0));
        o1.x = __uint_as_float(f2tf32(o[dt][2] * i1));
        o1.y = __uint_as_float(f2tf32(o[dt][3] * i1));
        *(float2*)&g_att[((long)(b * T_ + qg0)) * C_ + h * D_ + d] = o0;
        *(float2*)&g_att[((long)(b * T_ + qg1)) * C_ + h * D_ + d] = o1;
    }
}

// ---------------------------------------------------------------------------
// Launch. Inputs identified by element count (all distinct).
// ---------------------------------------------------------------------------
extern "C" void kernel_launch(void* const* d_in, const int* in_sizes, int n_in,
                              void* d_out, int out_size)
{
    const float* x      = 0;
    const float* qkv_w  = 0;
    const float* qkv_b  = 0;
    const float* proj_w = 0;
    const float* proj_b = 0;

    for (int i = 0; i < n_in; i++) {
        switch (in_sizes[i]) {
            case B_ * T_ * C_:  x      = (const float*)d_in[i]; break; // 8388608
            case T_ * T_:       /* attn_mask — unused */         break; // 4194304
            case 3 * C_ * C_:   qkv_w  = (const float*)d_in[i]; break; // 3145728
            case 3 * C_:        qkv_b  = (const float*)d_in[i]; break; // 3072
            case C_ * C_:       proj_w = (const float*)d_in[i]; break; // 1048576
            case C_:            proj_b = (const float*)d_in[i]; break; // 1024
        }
    }

    float* out = (float*)d_out;

    cudaFuncSetAttribute(gemm_cp<1>,
        cudaFuncAttributeMaxDynamicSharedMemorySize, GSMEM_BYTES);
    cudaFuncSetAttribute(gemm_cp<2>,
        cudaFuncAttributeMaxDynamicSharedMemorySize, GSMEM_BYTES);

    // Prepass: round operands to tf32 bits in gmem
    round_tf32<0><<<2048, 256>>>((const float4*)x,      (B_*T_*C_) / 4);
    round_tf32<1><<<1024, 256>>>((const float4*)qkv_w,  (3*C_*C_) / 4);
    round_tf32<2><<<512,  256>>>((const float4*)proj_w, (C_*C_) / 4);

    // QKV: g_xr [8192,1024] x g_wqkv [3072,1024]^T -> scatter q/k/v
    {
        dim3 grid(3 * C_ / 128, (B_ * T_) / 128);
        gemm_cp<1><<<grid, 128, GSMEM_BYTES>>>(qkv_b, nullptr,
                                               B_ * T_, 3 * C_, C_);
    }
    // Attention (tensor-core)
    {
        dim3 grid(T_ / QT, H_, B_);
        attn_mma_kernel<<<grid, 256>>>();
    }
    // Proj: g_att [8192,1024] x g_wproj [1024,1024]^T -> out
    {
        dim3 grid(C_ / 128, (B_ * T_) / 128);
        gemm_cp<2><<<grid, 128, GSMEM_BYTES>>>(proj_b, out,
                                               B_ * T_, C_, C_);
    }
}

// round 13
// speedup vs baseline: 1.1422x; 1.0703x over previous
#include <cuda_runtime.h>
#include <math.h>
#include <stdint.h>

#define B_    4
#define T_    2048
#define C_    1024
#define H_    16
#define D_    64
#define WIN_  256

// Scratch (device globals; no runtime allocation allowed)
__device__ float g_q[B_*H_*T_*D_];
__device__ float g_k[B_*H_*T_*D_];
__device__ float g_v[B_*H_*T_*D_];
__device__ __align__(16) float g_att[B_*T_*C_];
// Pre-rounded (tf32-in-fp32-bits) operand copies
__device__ __align__(16) float g_xr[B_*T_*C_];
__device__ __align__(16) float g_wqkv[3*C_*C_];
__device__ __align__(16) float g_wproj[C_*C_];

__device__ __forceinline__ uint32_t f2tf32(float x) {
    uint32_t r;
    asm("cvt.rna.tf32.f32 %0, %1;" : "=r"(r) : "f"(x));
    return r;
}

__device__ __forceinline__ void mma_tf32_16x8x8(
    float* d, const uint32_t* a, const uint32_t* b)
{
    asm volatile(
        "mma.sync.aligned.m16n8k8.row.col.f32.tf32.tf32.f32 "
        "{%0,%1,%2,%3}, {%4,%5,%6,%7}, {%8,%9}, {%0,%1,%2,%3};"
        : "+f"(d[0]), "+f"(d[1]), "+f"(d[2]), "+f"(d[3])
        : "r"(a[0]), "r"(a[1]), "r"(a[2]), "r"(a[3]),
          "r"(b[0]), "r"(b[1]));
}

__device__ __forceinline__ uint32_t smem_u32(const void* p) {
    uint32_t a;
    asm("{ .reg .u64 t; cvta.to.shared.u64 t, %1; cvt.u32.u64 %0, t; }"
        : "=r"(a) : "l"(p));
    return a;
}

__device__ __forceinline__ void cp16(uint32_t s, const void* g) {
    asm volatile("cp.async.cg.shared.global [%0], [%1], 16;"
                 :: "r"(s), "l"(g));
}
#define CP_COMMIT() asm volatile("cp.async.commit_group;" ::: "memory")
#define CP_WAIT(n)  asm volatile("cp.async.wait_group %0;" :: "n"(n) : "memory")

// ---------------------------------------------------------------------------
// Prepass: round fp32 -> tf32 bits in gmem.
// ---------------------------------------------------------------------------
template<int SEL>
__global__ void round_tf32(const float4* __restrict__ src, int n4)
{
    float4* dst = (SEL == 0) ? (float4*)g_xr
                : (SEL == 1) ? (float4*)g_wqkv : (float4*)g_wproj;
    for (int i = blockIdx.x * blockDim.x + threadIdx.x; i < n4;
         i += gridDim.x * blockDim.x) {
        float4 v = src[i];
        v.x = __uint_as_float(f2tf32(v.x));
        v.y = __uint_as_float(f2tf32(v.y));
        v.z = __uint_as_float(f2tf32(v.z));
        v.w = __uint_as_float(f2tf32(v.w));
        dst[i] = v;
    }
}

// ---------------------------------------------------------------------------
// tf32 GEMM, NT. 128 threads, CTA tile 128x128x32, warp tile 64x64.
// 3-STAGE cp.async pipeline, ONE barrier per chunk, issue AFTER the barrier:
// the buffer written at iter c ((c+2)%3 == (c-1)%3) was last read at iter
// c-1, whose readers all passed this iter's barrier -> no trailing barrier.
// MODE 1: A=g_xr, B=g_wqkv, scatter q/k/v PRE-ROUNDED to tf32 bits
//         (attention cp.asyncs them raw; unrounded would truncate in mma).
// MODE 2: A=g_att (already tf32 bits), B=g_wproj, plain fp32 out.
// ---------------------------------------------------------------------------
#define KPAD 36
#define BUFW (2 * 128 * KPAD)                 // words per stage (A+B)
#define GSMEM_BYTES (3 * BUFW * 4)            // 110592 B

template<int MODE>
__global__ __launch_bounds__(128, 2) void gemm_cp(
    const float* __restrict__ bias,
    float* __restrict__ Cout,
    int M, int N, int K)
{
    extern __shared__ uint32_t sm[];
    const uint32_t sbase = smem_u32(sm);

    const float* __restrict__ A  = (MODE == 1) ? g_xr   : (const float*)g_att;
    const float* __restrict__ Bw = (MODE == 1) ? g_wqkv : g_wproj;

    const int tid  = threadIdx.x;
    const int w    = tid >> 5;
    const int lane = tid & 31;
    const int g    = lane >> 2;
    const int q    = lane & 3;
    const int wm   = w & 1;
    const int wn   = w >> 1;
    const int m0   = blockIdx.y * 128;
    const int n0   = blockIdx.x * 128;

    float acc[4][8][4];
    #pragma unroll
    for (int i = 0; i < 4; i++)
        #pragma unroll
        for (int j = 0; j < 8; j++)
            #pragma unroll
            for (int r = 0; r < 4; r++) acc[i][j][r] = 0.f;

    const int nch = K / 32;

    // issue chunk 'cc' into stage cc%3
    auto issue = [&](int cc) {
        const int k0 = cc * 32;
        const uint32_t as = sbase + (cc % 3) * BUFW * 4;
        const uint32_t bs = as + 128 * KPAD * 4;
        #pragma unroll
        for (int it = 0; it < 8; it++) {
            int f   = tid + it * 128;
            int row = f >> 3;
            int k4  = (f & 7) << 2;
            const uint32_t so = (uint32_t)(row * KPAD + k4) * 4;
            cp16(as + so, &A [(long)(m0 + row) * K + k0 + k4]);
            cp16(bs + so, &Bw[(long)(n0 + row) * K + k0 + k4]);
        }
        CP_COMMIT();
    };

    issue(0);
    issue(1);

    for (int c = 0; c < nch; c++) {
        if (c + 1 < nch) { CP_WAIT(1); } else { CP_WAIT(0); }
        __syncthreads();
        if (c + 2 < nch) issue(c + 2);

        const uint32_t* As = sm + (c % 3) * BUFW;
        const uint32_t* Bs = As + 128 * KPAD;

        #pragma unroll
        for (int kk = 0; kk < 4; kk++) {
            const int kb = kk * 8;
            uint32_t af[4][4], bf[8][2];
            #pragma unroll
            for (int im = 0; im < 4; im++) {
                const int mr = wm * 64 + im * 16 + g;
                af[im][0] = As[ mr      * KPAD + kb + q];
                af[im][1] = As[(mr + 8) * KPAD + kb + q];
                af[im][2] = As[ mr      * KPAD + kb + q + 4];
                af[im][3] = As[(mr + 8) * KPAD + kb + q + 4];
            }
            #pragma unroll
            for (int in = 0; in < 8; in++) {
                const int nc = wn * 64 + in * 8 + g;
                bf[in][0] = Bs[nc * KPAD + kb + q];
                bf[in][1] = Bs[nc * KPAD + kb + q + 4];
            }
            #pragma unroll
            for (int im = 0; im < 4; im++)
                #pragma unroll
                for (int in = 0; in < 8; in++)
                    mma_tf32_16x8x8(acc[im][in], af[im], bf[in]);
        }
    }

    // Epilogue
    #pragma unroll
    for (int im = 0; im < 4; im++) {
        #pragma unroll
        for (int in = 0; in < 8; in++) {
            const int mbase = m0 + wm * 64 + im * 16 + g;
            const int nbase = n0 + wn * 64 + in * 8 + q * 2;
            #pragma unroll
            for (int r = 0; r < 4; r++) {
                const int m = mbase + (r >> 1) * 8;
                const int n = nbase + (r & 1);
                float v = acc[im][in][r] + bias[n];
                if (MODE == 1) {
                    int s = n >> 10;
                    int h = (n >> 6) & 15;
                    int d = n & 63;
                    int b = m >> 11;
                    int t = m & 2047;
                    float* dst = (s == 0) ? g_q : (s == 1 ? g_k : g_v);
                    // pre-round so attention's raw cp.async feeds RN tf32
                    dst[(((long)(b * H_ + h)) * T_ + t) * D_ + d] =
                        __uint_as_float(f2tf32(v));
                } else {
                    Cout[(long)m * N + n] = v;
                }
            }
        }
    }
}

// ---------------------------------------------------------------------------
// Tensor-core windowed attention, 3-stage cp.async, ONE barrier per chunk.
// 256 threads (8 warps), QT=128 queries per CTA, warp owns 16 queries,
// Q resident in registers as tf32 frags (log2e folded -> exp2f softmax).
// K and V staged ROW-MAJOR [key][68] via cp.async (data pre-rounded by the
// QKV epilogue). p_s pad 36 -> conflict-free PV A-frag reads.
// ---------------------------------------------------------------------------
#define QT  128
#define CK2 32
#define AST (2 * CK2 * 68)                 // words per stage (K+V)
#define ASMEM_BYTES (3 * AST * 4)          // 52224 B

__global__ __launch_bounds__(256, 2) void attn_mma_kernel()
{
    extern __shared__ uint32_t dsm[];
    __shared__ uint32_t p_s[8][16][36];

    const uint32_t sbase = smem_u32(dsm);
    const int tid  = threadIdx.x;
    const int w    = tid >> 5;
    const int lane = tid & 31;
    const int g    = lane >> 2;
    const int q    = lane & 3;
    const int q0   = blockIdx.x * QT;
    const int h    = blockIdx.y;
    const int b    = blockIdx.z;

    const long bh   = (long)(b * H_ + h);
    const float* Qp = g_q + bh * T_ * D_;
    const float* Kp = g_k + bh * T_ * D_;
    const float* Vp = g_v + bh * T_ * D_;

    const int qw  = q0 + w * 16;
    const int qg0 = qw + g;
    const int qg1 = qw + g + 8;

    // Q frags; fold scale*log2e so softmax uses exp2f
    const float SC = 0.18033688011f;   // 0.125 * log2(e)
    uint32_t aq[8][4];
    #pragma unroll
    for (int kk = 0; kk < 8; kk++) {
        aq[kk][0] = f2tf32(Qp[(long)qg0 * D_ + kk * 8 + q    ] * SC);
        aq[kk][1] = f2tf32(Qp[(long)qg1 * D_ + kk * 8 + q    ] * SC);
        aq[kk][2] = f2tf32(Qp[(long)qg0 * D_ + kk * 8 + q + 4] * SC);
        aq[kk][3] = f2tf32(Qp[(long)qg1 * D_ + kk * 8 + q + 4] * SC);
    }

    int lo_blk = q0 - (WIN_ - 1);
    if (lo_blk < 0) lo_blk = 0;
    lo_blk &= ~(CK2 - 1);
    const int nchunks = ((q0 + QT - 1) - lo_blk) / CK2 + 1;   // >= 4

    // issue chunk cc (keys [lo_blk+32cc, +31]) into stage cc%3
    auto issue = [&](int cc) {
        const int ks = lo_blk + cc * CK2;
        const uint32_t kb = sbase + (cc % 3) * AST * 4;
        #pragma unroll
        for (int it = 0; it < 4; it++) {
            int f   = tid + it * 256;        // 0..1023
            int mat = f >> 9;                // 0:K 1:V
            int idx = f & 511;
            int row = idx >> 4;              // key 0..31
            int c4  = (idx & 15) << 2;       // dim quad
            const float* src = (mat ? Vp : Kp) + (long)(ks + row) * D_ + c4;
            cp16(kb + (uint32_t)(mat * (CK2 * 68) + row * 68 + c4) * 4, src);
        }
        CP_COMMIT();
    };

    float o[8][4];
    #pragma unroll
    for (int dt = 0; dt < 8; dt++)
        #pragma unroll
        for (int r = 0; r < 4; r++) o[dt][r] = 0.f;
    float m0r = -1e30f, m1r = -1e30f, l0 = 0.f, l1 = 0.f;

    issue(0);
    issue(1);

    for (int c = 0; c < nchunks; c++) {
        if (c + 1 < nchunks) { CP_WAIT(1); } else { CP_WAIT(0); }
        __syncthreads();
        if (c + 2 < nchunks) issue(c + 2);

        const int ks = lo_blk + c * CK2;
        if (ks > qw + 15 || ks + CK2 - 1 < qw - (WIN_ - 1)) continue;

        const uint32_t* ks_ = dsm + (c % 3) * AST;
        const uint32_t* vs_ = ks_ + CK2 * 68;

        // S = Q*K^T
        float s[4][4];
        #pragma unroll
        for (int nt = 0; nt < 4; nt++)
            #pragma unroll
            for (int r = 0; r < 4; r++) s[nt][r] = 0.f;
        #pragma unroll
        for (int kk = 0; kk < 8; kk++) {
            uint32_t bf[4][2];
            #pragma unroll
            for (int nt = 0; nt < 4; nt++) {
                bf[nt][0] = ks_[(nt * 8 + g) * 68 + kk * 8 + q];
                bf[nt][1] = ks_[(nt * 8 + g) * 68 + kk * 8 + q + 4];
            }
            #pragma unroll
            for (int nt = 0; nt < 4; nt++)
                mma_tf32_16x8x8(s[nt], aq[kk], bf[nt]);
        }

        // Mask: valid iff 0 <= q - j < WIN
        #pragma unroll
        for (int nt = 0; nt < 4; nt++) {
            const int j0 = ks + nt * 8 + 2 * q;
            const int j1 = j0 + 1;
            s[nt][0] = ((unsigned)(qg0 - j0) < WIN_) ? s[nt][0] : -1e30f;
            s[nt][1] = ((unsigned)(qg0 - j1) < WIN_) ? s[nt][1] : -1e30f;
            s[nt][2] = ((unsigned)(qg1 - j0) < WIN_) ? s[nt][2] : -1e30f;
            s[nt][3] = ((unsigned)(qg1 - j1) < WIN_) ? s[nt][3] : -1e30f;
        }

        float cm0 = -1e30f, cm1 = -1e30f;
        #pragma unroll
        for (int nt = 0; nt < 4; nt++) {
            cm0 = fmaxf(cm0, fmaxf(s[nt][0], s[nt][1]));
            cm1 = fmaxf(cm1, fmaxf(s[nt][2], s[nt][3]));
        }
        cm0 = fmaxf(cm0, __shfl_xor_sync(0xffffffffu, cm0, 1));
        cm0 = fmaxf(cm0, __shfl_xor_sync(0xffffffffu, cm0, 2));
        cm1 = fmaxf(cm1, __shfl_xor_sync(0xffffffffu, cm1, 1));
        cm1 = fmaxf(cm1, __shfl_xor_sync(0xffffffffu, cm1, 2));

        const float m0n = fmaxf(m0r, cm0), m1n = fmaxf(m1r, cm1);
        const float c0  = exp2f(m0r - m0n), c1 = exp2f(m1r - m1n);

        float p[4][4];
        float ps0 = 0.f, ps1 = 0.f;
        #pragma unroll
        for (int nt = 0; nt < 4; nt++) {
            p[nt][0] = exp2f(s[nt][0] - m0n);
            p[nt][1] = exp2f(s[nt][1] - m0n);
            p[nt][2] = exp2f(s[nt][2] - m1n);
            p[nt][3] = exp2f(s[nt][3] - m1n);
            ps0 += p[nt][0] + p[nt][1];
            ps1 += p[nt][2] + p[nt][3];
        }
        ps0 += __shfl_xor_sync(0xffffffffu, ps0, 1);
        ps0 += __shfl_xor_sync(0xffffffffu, ps0, 2);
        ps1 += __shfl_xor_sync(0xffffffffu, ps1, 1);
        ps1 += __shfl_xor_sync(0xffffffffu, ps1, 2);

        l0 = l0 * c0 + ps0;  m0r = m0n;
        l1 = l1 * c1 + ps1;  m1r = m1n;
        #pragma unroll
        for (int dt = 0; dt < 8; dt++) {
            o[dt][0] *= c0;  o[dt][1] *= c0;
            o[dt][2] *= c1;  o[dt][3] *= c1;
        }

        // P -> per-warp smem (tf32 bits), C-layout
        #pragma unroll
        for (int nt = 0; nt < 4; nt++) {
            uint2 u0, u1;
            u0.x = f2tf32(p[nt][0]); u0.y = f2tf32(p[nt][1]);
            u1.x = f2tf32(p[nt][2]); u1.y = f2tf32(p[nt][3]);
            *(uint2*)&p_s[w][g    ][nt * 8 + 2 * q] = u0;
            *(uint2*)&p_s[w][g + 8][nt * 8 + 2 * q] = u1;
        }
        __syncwarp();

        // O += P * V  (V row-major [key][68]; B elem (n=dim,k=key) = vs_[key][dim])
        #pragma unroll
        for (int kk = 0; kk < 4; kk++) {
            uint32_t ap[4];
            ap[0] = p_s[w][g    ][kk * 8 + q];
            ap[1] = p_s[w][g + 8][kk * 8 + q];
            ap[2] = p_s[w][g    ][kk * 8 + q + 4];
            ap[3] = p_s[w][g + 8][kk * 8 + q + 4];
            #pragma unroll
            for (int dt = 0; dt < 8; dt++) {
                uint32_t bv[2];
                bv[0] = vs_[(kk * 8 + q    ) * 68 + dt * 8 + g];
                bv[1] = vs_[(kk * 8 + q + 4) * 68 + dt * 8 + g];
                mma_tf32_16x8x8(o[dt], ap, bv);
            }
        }
        __syncwarp();
    }

    // Epilogue: store PRE-ROUNDED tf32 bits (proj GEMM consumes directly)
    const float i0 = 1.f / l0, i1 = 1.f / l1;
    #pragma unroll
    for (int dt = 0; dt < 8; dt++) {
        const int d = dt * 8 + 2 * q;
        float2 o0, o1;
        o0.x = __uint_as_float(f2tf32(o[dt][0] * i0));
        o0.y = __uint_as_float(f2tf32(o[dt][1] * i0));
        o1.x = __uint_as_float(f2tf32(o[dt][2] * i1));
        o1.y = __uint_as_float(f2tf32(o[dt][3] * i1));
        *(float2*)&g_att[((long)(b * T_ + qg0)) * C_ + h * D_ + d] = o0;
        *(float2*)&g_att[((long)(b * T_ + qg1)) * C_ + h * D_ + d] = o1;
    }
}

// ---------------------------------------------------------------------------
// Launch. Inputs identified by element count (all distinct).
// ---------------------------------------------------------------------------
extern "C" void kernel_launch(void* const* d_in, const int* in_sizes, int n_in,
                              void* d_out, int out_size)
{
    const float* x      = 0;
    const float* qkv_w  = 0;
    const float* qkv_b  = 0;
    const float* proj_w = 0;
    const float* proj_b = 0;

    for (int i = 0; i < n_in; i++) {
        switch (in_sizes[i]) {
            case B_ * T_ * C_:  x      = (const float*)d_in[i]; break; // 8388608
            case T_ * T_:       /* attn_mask — unused */         break; // 4194304
            case 3 * C_ * C_:   qkv_w  = (const float*)d_in[i]; break; // 3145728
            case 3 * C_:        qkv_b  = (const float*)d_in[i]; break; // 3072
            case C_ * C_:       proj_w = (const float*)d_in[i]; break; // 1048576
            case C_:            proj_b = (const float*)d_in[i]; break; // 1024
        }
    }

    float* out = (float*)d_out;

    cudaFuncSetAttribute(gemm_cp<1>,
        cudaFuncAttributeMaxDynamicSharedMemorySize, GSMEM_BYTES);
    cudaFuncSetAttribute(gemm_cp<2>,
        cudaFuncAttributeMaxDynamicSharedMemorySize, GSMEM_BYTES);
    cudaFuncSetAttribute(attn_mma_kernel,
        cudaFuncAttributeMaxDynamicSharedMemorySize, ASMEM_BYTES);

    // Prepass: round operands to tf32 bits in gmem
    round_tf32<0><<<2048, 256>>>((const float4*)x,      (B_*T_*C_) / 4);
    round_tf32<1><<<1024, 256>>>((const float4*)qkv_w,  (3*C_*C_) / 4);
    round_tf32<2><<<512,  256>>>((const float4*)proj_w, (C_*C_) / 4);

    // QKV: g_xr [8192,1024] x g_wqkv [3072,1024]^T -> scatter q/k/v (rounded)
    {
        dim3 grid(3 * C_ / 128, (B_ * T_) / 128);
        gemm_cp<1><<<grid, 128, GSMEM_BYTES>>>(qkv_b, nullptr,
                                               B_ * T_, 3 * C_, C_);
    }
    // Attention (tensor-core, 3-stage cp.async)
    {
        dim3 grid(T_ / QT, H_, B_);
        attn_mma_kernel<<<grid, 256, ASMEM_BYTES>>>();
    }
    // Proj: g_att [8192,1024] x g_wproj [1024,1024]^T -> out
    {
        dim3 grid(C_ / 128, (B_ * T_) / 128);
        gemm_cp<2><<<grid, 128, GSMEM_BYTES>>>(proj_b, out,
                                               B_ * T_, C_, C_);
    }
}